// round 2
// baseline (speedup 1.0000x reference)
#include <cuda_runtime.h>
#include <cuda_bf16.h>

// FlowUpSampler: convex upsampling (RAFT-style), float4 / wide-load version.
// flow: [N=8, 2, H=64, W=128] f32
// mask: [N, 9*8*8=576, H, W] f32, layout [n][k][a][b][h][w]
// out:  [N, 2, 8H=512, 8W=1024] f32, out[n][c][8h+a][8w+b]
//
// 1 warp per block, block = (n, a, h). Each lane owns 4 consecutive w.
// Per b: 9 x LDG.128 front-batched (4.6 KB/warp in flight) -> softmax ->
// convex combine -> stage to smem; final phase does coalesced float4 stores.

#define H_ 64
#define W_ 128

__global__ __launch_bounds__(32, 16)
void flow_up_kernel(const float* __restrict__ flow,
                    const float* __restrict__ mask,
                    float* __restrict__ out)
{
    const int l   = threadIdx.x;          // 0..31, w4 lane
    const int bid = blockIdx.x;
    const int h = bid & (H_ - 1);
    const int a = (bid >> 6) & 7;
    const int n = bid >> 9;

    __shared__ float sf[2][3][132];       // flow*8, rows h-1..h+1, halo'd; stride 132 keeps rows 16B-aligned
    __shared__ float so[2][8][W_];        // output staging [c][b][w]

    // cooperative load of the 3-row flow slab (zero-padded), pre-scaled by 8
    for (int i = l; i < 2 * 3 * 132; i += 32) {
        int c  = i / 396;
        int r  = (i / 132) % 3;
        int x  = i % 132;
        int hh = h - 1 + r;
        int ww = x - 1;
        float v = 0.0f;
        if ((unsigned)hh < H_ && (unsigned)ww < W_)
            v = 8.0f * flow[(((size_t)n * 2 + c) * H_ + hh) * W_ + ww];
        sf[c][r][x] = v;
    }
    __syncwarp();

    // Sliding patch windows: for lane l (w = 4l..4l+3), per (c,di) need
    // sf[c][di][4l .. 4l+5]; component i, kernel col dj -> P[di][i+dj].
    float P0[3][6], P1[3][6];
#pragma unroll
    for (int di = 0; di < 3; di++) {
        float4 v = *reinterpret_cast<const float4*>(&sf[0][di][4 * l]);
        P0[di][0] = v.x; P0[di][1] = v.y; P0[di][2] = v.z; P0[di][3] = v.w;
        P0[di][4] = sf[0][di][4 * l + 4];
        P0[di][5] = sf[0][di][4 * l + 5];
        float4 u = *reinterpret_cast<const float4*>(&sf[1][di][4 * l]);
        P1[di][0] = u.x; P1[di][1] = u.y; P1[di][2] = u.z; P1[di][3] = u.w;
        P1[di][4] = sf[1][di][4 * l + 4];
        P1[di][5] = sf[1][di][4 * l + 5];
    }

    // mask in float4 units: element (n,k,a,b,h,w) -> f4 index
    // ((n*576 + k*64 + a*8 + b) * 8192 + h*128 + 4*l) / 4
    const size_t HW4 = 2048;              // 8192 floats / 4
    const float4* mp4 = reinterpret_cast<const float4*>(mask)
        + ((size_t)n * 576 + (size_t)a * 8) * HW4 + (size_t)h * 32 + l;

#pragma unroll
    for (int b = 0; b < 8; b++) {
        const float4* mb = mp4 + (size_t)b * HW4;
        float4 m[9];
#pragma unroll
        for (int k = 0; k < 9; k++)
            m[k] = __ldcs(mb + (size_t)k * 64 * HW4);   // streaming: no reuse

        float4 s  = make_float4(0.f, 0.f, 0.f, 0.f);
        float4 A0 = s, A1 = s;
#pragma unroll
        for (int k = 0; k < 9; k++) {
            const int di = k / 3, dj = k % 3;
            float4 e;
            e.x = __expf(m[k].x);  e.y = __expf(m[k].y);
            e.z = __expf(m[k].z);  e.w = __expf(m[k].w);
            s.x += e.x; s.y += e.y; s.z += e.z; s.w += e.w;
            A0.x = fmaf(e.x, P0[di][dj + 0], A0.x);
            A0.y = fmaf(e.y, P0[di][dj + 1], A0.y);
            A0.z = fmaf(e.z, P0[di][dj + 2], A0.z);
            A0.w = fmaf(e.w, P0[di][dj + 3], A0.w);
            A1.x = fmaf(e.x, P1[di][dj + 0], A1.x);
            A1.y = fmaf(e.y, P1[di][dj + 1], A1.y);
            A1.z = fmaf(e.z, P1[di][dj + 2], A1.z);
            A1.w = fmaf(e.w, P1[di][dj + 3], A1.w);
        }
        float4 r;
        r.x = __fdividef(1.f, s.x);  r.y = __fdividef(1.f, s.y);
        r.z = __fdividef(1.f, s.z);  r.w = __fdividef(1.f, s.w);

        float4 o0 = make_float4(A0.x * r.x, A0.y * r.y, A0.z * r.z, A0.w * r.w);
        float4 o1 = make_float4(A1.x * r.x, A1.y * r.y, A1.z * r.z, A1.w * r.w);
        *reinterpret_cast<float4*>(&so[0][b][4 * l]) = o0;
        *reinterpret_cast<float4*>(&so[1][b][4 * l]) = o1;
    }
    __syncwarp();

    // Coalesced store phase: out[n][c][8h+a][o], o = 8w+b, value = so[c][o&7][o>>3]
    float4* out4 = reinterpret_cast<float4*>(out);
#pragma unroll
    for (int c = 0; c < 2; c++) {
        const size_t base = (((size_t)(n * 2 + c) * (8 * H_)) + (size_t)8 * h + a) * (8 * W_ / 4);
#pragma unroll
        for (int j = 0; j < 8; j++) {
            const int idx = j * 32 + l;          // float4 index within the 1024-row
            const int w   = idx >> 1;            // o = 4*idx -> w = o>>3
            const int b0  = (l & 1) * 4;         // o&7 base
            float4 v = make_float4(so[c][b0 + 0][w], so[c][b0 + 1][w],
                                   so[c][b0 + 2][w], so[c][b0 + 3][w]);
            out4[base + idx] = v;
        }
    }
}

extern "C" void kernel_launch(void* const* d_in, const int* in_sizes, int n_in,
                              void* d_out, int out_size)
{
    const float* flow = (const float*)d_in[0];
    const float* mask = (const float*)d_in[1];
    float* out = (float*)d_out;
    (void)in_sizes; (void)n_in; (void)out_size;

    // grid = N * 8 (a) * H = 4096 blocks, 1 warp each
    flow_up_kernel<<<4096, 32>>>(flow, mask, out);
}